// round 8
// baseline (speedup 1.0000x reference)
#include <cuda_runtime.h>

#define BB 4
#define CC 512
#define TT 1024
#define HH 8
#define DD 64
#define WW 4

typedef unsigned long long u64;

// ---------------- device scratch (no runtime allocation allowed) ----------------
__device__ float g_Q [BB*CC*TT];   // [B][C][T]
__device__ float g_K [BB*CC*TT];
__device__ float g_V [BB*CC*TT];
__device__ float g_AO[BB*CC*TT];

// ---------------- packed f32x2 helpers ----------------
__device__ __forceinline__ u64 pk2(float x, float y) {
    u64 r; asm("mov.b64 %0, {%1, %2};" : "=l"(r) : "f"(x), "f"(y)); return r;
}
__device__ __forceinline__ u64 dup2(float x) {
    u64 r; asm("mov.b64 %0, {%1, %1};" : "=l"(r) : "f"(x)); return r;
}
__device__ __forceinline__ void fma2(u64 &d, u64 a, u64 b) {
    asm("fma.rn.f32x2 %0, %1, %2, %0;" : "+l"(d) : "l"(a), "l"(b));
}
__device__ __forceinline__ void mul2(u64 &d, u64 a) {
    asm("mul.rn.f32x2 %0, %0, %1;" : "+l"(d) : "l"(a));
}
__device__ __forceinline__ float2 upk2(u64 v) {
    float2 f; asm("mov.b64 {%0, %1}, %2;" : "=f"(f.x), "=f"(f.y) : "l"(v)); return f;
}

// =====================================================================
// 128x128x16 SGEMM, double-buffered smem, f32x2 core. (unchanged)
// =====================================================================
__device__ __forceinline__ void gemm128(const float* __restrict__ Xb,
                                        const float* __restrict__ Wm,
                                        const float* __restrict__ bias,
                                        float* __restrict__ Yb,
                                        int o0, int t0)
{
    __shared__ float As[2][16][132];
    __shared__ float Bs[2][16][132];

    const int tid = threadIdx.x;
    const int ty  = tid >> 4, tx = tid & 15;
    const int am  = tid >> 1;
    const int ak  = (tid & 1) << 3;
    const int bkr = tid >> 4;
    const int bn  = (tid & 15) << 3;

    const float* wp = Wm + (size_t)(o0 + am) * CC + ak;
    const float* xp = Xb + (size_t)bkr * TT + t0 + bn;

    u64 acc[4][8];
#pragma unroll
    for (int i = 0; i < 4; i++)
#pragma unroll
        for (int j = 0; j < 8; j++) acc[i][j] = 0ull;

    {
        float4 a0 = *(const float4*)(wp);
        float4 a1 = *(const float4*)(wp + 4);
        float4 b0 = *(const float4*)(xp);
        float4 b1 = *(const float4*)(xp + 4);
        As[0][ak+0][am]=a0.x; As[0][ak+1][am]=a0.y; As[0][ak+2][am]=a0.z; As[0][ak+3][am]=a0.w;
        As[0][ak+4][am]=a1.x; As[0][ak+5][am]=a1.y; As[0][ak+6][am]=a1.z; As[0][ak+7][am]=a1.w;
        *(float4*)&Bs[0][bkr][bn]     = b0;
        *(float4*)&Bs[0][bkr][bn + 4] = b1;
    }
    __syncthreads();

    const int NCH = CC / 16;
    for (int ch = 0; ch < NCH; ch++) {
        const int cur = ch & 1;
        float4 na0, na1, nb0, nb1;
        if (ch + 1 < NCH) {
            const float* wq = wp + (ch + 1) * 16;
            const float* xq = xp + (size_t)(ch + 1) * 16 * TT;
            na0 = *(const float4*)(wq);
            na1 = *(const float4*)(wq + 4);
            nb0 = *(const float4*)(xq);
            nb1 = *(const float4*)(xq + 4);
        }

#pragma unroll
        for (int k = 0; k < 16; k++) {
            float4 fa0 = *(const float4*)&As[cur][k][ty * 8];
            float4 fa1 = *(const float4*)&As[cur][k][ty * 8 + 4];
            float4 fb0 = *(const float4*)&Bs[cur][k][tx * 8];
            float4 fb1 = *(const float4*)&Bs[cur][k][tx * 8 + 4];
            u64 ap[4] = { pk2(fa0.x, fa0.y), pk2(fa0.z, fa0.w),
                          pk2(fa1.x, fa1.y), pk2(fa1.z, fa1.w) };
            float bb[8] = { fb0.x, fb0.y, fb0.z, fb0.w, fb1.x, fb1.y, fb1.z, fb1.w };
#pragma unroll
            for (int j = 0; j < 8; j++) {
                u64 bd = dup2(bb[j]);
#pragma unroll
                for (int i = 0; i < 4; i++) fma2(acc[i][j], ap[i], bd);
            }
        }

        if (ch + 1 < NCH) {
            const int nxt = cur ^ 1;
            As[nxt][ak+0][am]=na0.x; As[nxt][ak+1][am]=na0.y; As[nxt][ak+2][am]=na0.z; As[nxt][ak+3][am]=na0.w;
            As[nxt][ak+4][am]=na1.x; As[nxt][ak+5][am]=na1.y; As[nxt][ak+6][am]=na1.z; As[nxt][ak+7][am]=na1.w;
            *(float4*)&Bs[nxt][bkr][bn]     = nb0;
            *(float4*)&Bs[nxt][bkr][bn + 4] = nb1;
            __syncthreads();
        }
    }

#pragma unroll
    for (int i = 0; i < 4; i++) {
        const int o = o0 + ty * 8 + 2 * i;
        const float bl = bias[o], bh = bias[o + 1];
        float lo[8], hi[8];
#pragma unroll
        for (int j = 0; j < 8; j++) {
            float2 e = upk2(acc[i][j]);
            lo[j] = e.x + bl; hi[j] = e.y + bh;
        }
        float* y0 = Yb + (size_t)o * TT + t0 + tx * 8;
        float* y1 = y0 + TT;
        ((float4*)y0)[0] = make_float4(lo[0], lo[1], lo[2], lo[3]);
        ((float4*)y0)[1] = make_float4(lo[4], lo[5], lo[6], lo[7]);
        ((float4*)y1)[0] = make_float4(hi[0], hi[1], hi[2], hi[3]);
        ((float4*)y1)[1] = make_float4(hi[4], hi[5], hi[6], hi[7]);
    }
}

__global__ void __launch_bounds__(256, 2)
qkv_kernel(const float* __restrict__ x,
           const float* __restrict__ Wq, const float* __restrict__ bq,
           const float* __restrict__ Wk, const float* __restrict__ bk,
           const float* __restrict__ Wv, const float* __restrict__ bv)
{
    const int z = blockIdx.z;
    const int m = z % 3;
    const int b = z / 3;
    const float* Wm = (m == 0) ? Wq : (m == 1) ? Wk : Wv;
    const float* bm = (m == 0) ? bq : (m == 1) ? bk : bv;
    float* dst      = (m == 0) ? g_Q : (m == 1) ? g_K : g_V;
    gemm128(x + (size_t)b * CC * TT, Wm, bm, dst + (size_t)b * CC * TT,
            blockIdx.y << 7, blockIdx.x << 7);
}

__global__ void __launch_bounds__(256, 2)
outproj_kernel(const float* __restrict__ Wo, const float* __restrict__ bo,
               float* __restrict__ out)
{
    const int b = blockIdx.z;
    gemm128(g_AO + (size_t)b * CC * TT, Wo, bo, out + (size_t)b * CC * TT,
            blockIdx.y << 7, blockIdx.x << 7);
}

// =====================================================================
// Flash attention v3: CTA = (b,h, 128 query rows), 128-wide key tiles.
// 256 threads as 16(ty: 8 rows each) x 16(tx: 8 keys / 4 dims each).
// S: 8x8 micro-tile f32x2. PV: packed pairwise-over-c accumulation.
// =====================================================================
struct AttnSmem {
    float QsT[DD][136];    // [dim][query row 0..127], pre-scaled by 1/8
    float KsT[DD][136];    // [dim][key 0..127]
    float VsT[DD][136];    // [dim][key 0..127]
    float Ps [128][132];   // P [row][key]; epilogue reuses as [dim][row]
    float ek [9][DD];
    float ev [9][DD];
    float qrel[128][12];   // qrel[r][e] = (Q[t0+r]/8) . ek[e]
    int   msk[128];
};

__global__ void __launch_bounds__(256, 1)
attn_kernel(const int* __restrict__ maskp,
            const float* __restrict__ emk,
            const float* __restrict__ emv)
{
    extern __shared__ char sraw[];
    AttnSmem& sm = *reinterpret_cast<AttnSmem*>(sraw);

    const int tid = threadIdx.x;
    const int ty  = tid >> 4;   // 0..15 -> rows ty*8..+7
    const int tx  = tid & 15;   // 0..15 -> keys tx*8..+7 ; dims tx*4..+3
    const int bh  = blockIdx.y;
    const int b   = bh >> 3;
    const int h   = bh & 7;
    const int t0  = blockIdx.x << 7;

    const float* Qg = g_Q + ((size_t)b * CC + h * DD) * TT;
    const float* Kg = g_K + ((size_t)b * CC + h * DD) * TT;
    const float* Vg = g_V + ((size_t)b * CC + h * DD) * TT;

    for (int idx = tid; idx < 9 * DD; idx += 256) {
        (&sm.ek[0][0])[idx] = emk[idx];
        (&sm.ev[0][0])[idx] = emv[idx];
    }
    // Q tile: 64 dims x 128 rows, coalesced float4, pre-scaled by 1/8
    for (int idx = tid; idx < DD * 32; idx += 256) {
        const int j  = idx >> 5;
        const int r4 = (idx & 31) << 2;
        float4 q = *(const float4*)&Qg[(size_t)j * TT + t0 + r4];
        q.x *= 0.125f; q.y *= 0.125f; q.z *= 0.125f; q.w *= 0.125f;
        *(float4*)&sm.QsT[j][r4] = q;
    }
    __syncthreads();

    // qrel[r][e] = (Q/8) . ek[e]
    for (int idx = tid; idx < 128 * 9; idx += 256) {
        const int r = idx & 127;
        const int e = idx >> 7;
        float s = 0.0f;
#pragma unroll 8
        for (int j = 0; j < DD; j++) s += sm.QsT[j][r] * sm.ek[e][j];
        sm.qrel[r][e] = s;
    }

    float mrun[8], lrun[8];
    u64 O2[8][4];   // [local row][dim], packed pairwise over key index
#pragma unroll
    for (int i = 0; i < 8; i++) { mrun[i] = -1e30f; lrun[i] = 0.0f; }
#pragma unroll
    for (int i = 0; i < 8; i++)
#pragma unroll
        for (int d = 0; d < 4; d++) O2[i][d] = 0ull;

    for (int c0 = 0; c0 < TT; c0 += 128) {
        __syncthreads();   // qrel / previous tile's Ps,VsT reads complete
        for (int idx = tid; idx < DD * 32; idx += 256) {
            const int j  = idx >> 5;
            const int c4 = (idx & 31) << 2;
            *(float4*)&sm.KsT[j][c4] = *(const float4*)&Kg[(size_t)j * TT + c0 + c4];
            *(float4*)&sm.VsT[j][c4] = *(const float4*)&Vg[(size_t)j * TT + c0 + c4];
        }
        if (tid < 128) sm.msk[tid] = maskp[b * TT + c0 + tid];
        __syncthreads();

        // ---- S = (Q/8) K^T : 8x8 micro-tile, rows packed in pairs ----
        u64 sv2[4][8];
#pragma unroll
        for (int p = 0; p < 4; p++)
#pragma unroll
            for (int j = 0; j < 8; j++) sv2[p][j] = 0ull;

#pragma unroll 8
        for (int j = 0; j < DD; j++) {
            float4 a0 = *(const float4*)&sm.QsT[j][ty * 8];
            float4 a1 = *(const float4*)&sm.QsT[j][ty * 8 + 4];
            float4 k0 = *(const float4*)&sm.KsT[j][tx * 8];
            float4 k1 = *(const float4*)&sm.KsT[j][tx * 8 + 4];
            u64 ap[4] = { pk2(a0.x, a0.y), pk2(a0.z, a0.w),
                          pk2(a1.x, a1.y), pk2(a1.z, a1.w) };
            float bb[8] = { k0.x, k0.y, k0.z, k0.w, k1.x, k1.y, k1.z, k1.w };
#pragma unroll
            for (int jj = 0; jj < 8; jj++) {
                u64 bd = dup2(bb[jj]);
#pragma unroll
                for (int p = 0; p < 4; p++) fma2(sv2[p][jj], ap[p], bd);
            }
        }

        // ---- per-row: band + mask + online softmax + write P ----
        float f[8];
#pragma unroll
        for (int p = 0; p < 4; p++) {
            float rv[2][8];
#pragma unroll
            for (int jj = 0; jj < 8; jj++) {
                float2 e = upk2(sv2[p][jj]);
                rv[0][jj] = e.x;
                rv[1][jj] = e.y;
            }
#pragma unroll
            for (int hf = 0; hf < 2; hf++) {
                const int i = p * 2 + hf;          // local row 0..7
                const int r = ty * 8 + i;          // CTA row 0..127
                const int t = t0 + r;
                float* v = rv[hf];
#pragma unroll
                for (int jj = 0; jj < 8; jj++) {
                    const int s = c0 + tx * 8 + jj;
                    const int e = s - t + WW;
                    if (e >= 0 && e <= 2 * WW) v[jj] += sm.qrel[r][e];
                    if (sm.msk[tx * 8 + jj] == 0) v[jj] = -10000.0f;
                }
                float tm = fmaxf(fmaxf(fmaxf(v[0], v[1]), fmaxf(v[2], v[3])),
                                 fmaxf(fmaxf(v[4], v[5]), fmaxf(v[6], v[7])));
#pragma unroll
                for (int o = 1; o < 16; o <<= 1)
                    tm = fmaxf(tm, __shfl_xor_sync(0xffffffffu, tm, o));
                const float mn = fmaxf(mrun[i], tm);
                f[i] = __expf(mrun[i] - mn);
                mrun[i] = mn;
                float rs = 0.0f;
#pragma unroll
                for (int jj = 0; jj < 8; jj++) {
                    const float pe = __expf(v[jj] - mn);
                    v[jj] = pe;
                    rs += pe;
                }
#pragma unroll
                for (int o = 1; o < 16; o <<= 1)
                    rs += __shfl_xor_sync(0xffffffffu, rs, o);
                lrun[i] = lrun[i] * f[i] + rs;
                *(float4*)&sm.Ps[r][tx * 8]     = make_float4(v[0], v[1], v[2], v[3]);
                *(float4*)&sm.Ps[r][tx * 8 + 4] = make_float4(v[4], v[5], v[6], v[7]);
            }
        }

        // rescale O accumulators
#pragma unroll
        for (int i = 0; i < 8; i++) {
            u64 fd = dup2(f[i]);
#pragma unroll
            for (int d = 0; d < 4; d++) mul2(O2[i][d], fd);
        }
        __syncthreads();   // full P tile visible

        // ---- O += P V : packed pairwise over key index, zero mov overhead ----
#pragma unroll 4
        for (int c = 0; c < 128; c += 4) {
            u64 va[4][2];
#pragma unroll
            for (int dd = 0; dd < 4; dd++) {
                float4 vv = *(const float4*)&sm.VsT[tx * 4 + dd][c];
                va[dd][0] = pk2(vv.x, vv.y);
                va[dd][1] = pk2(vv.z, vv.w);
            }
#pragma unroll
            for (int i = 0; i < 8; i++) {
                float4 pf = *(const float4*)&sm.Ps[ty * 8 + i][c];
                u64 pa0 = pk2(pf.x, pf.y);
                u64 pa1 = pk2(pf.z, pf.w);
#pragma unroll
                for (int dd = 0; dd < 4; dd++) {
                    fma2(O2[i][dd], pa0, va[dd][0]);
                    fma2(O2[i][dd], pa1, va[dd][1]);
                }
            }
        }

        // ---- band value term (lo lane only: final O = lo + hi) ----
        const int dc = c0 - t0;
        if (dc >= -128 && dc <= 128) {
#pragma unroll
            for (int e = 0; e <= 2 * WW; e++) {
                float4 e4 = *(const float4*)&sm.ev[e][tx * 4];
                u64 ed[4] = { dup2(e4.x), dup2(e4.y), dup2(e4.z), dup2(e4.w) };
#pragma unroll
                for (int i = 0; i < 8; i++) {
                    const int c = t0 + ty * 8 + i + e - WW - c0;
                    if (c >= 0 && c < 128) {
                        u64 pp = pk2(sm.Ps[ty * 8 + i][c], 0.0f);
#pragma unroll
                        for (int dd = 0; dd < 4; dd++) fma2(O2[i][dd], pp, ed[dd]);
                    }
                }
            }
        }
    }

    // ---- epilogue: O = (lo+hi)/l, stage transposed, coalesced store ----
    __syncthreads();
    float* Es = &sm.Ps[0][0];   // reuse as [dim][132-stride rows]
#pragma unroll
    for (int i = 0; i < 8; i++) {
        const float inv = 1.0f / lrun[i];
        const int r = ty * 8 + i;
#pragma unroll
        for (int dd = 0; dd < 4; dd++) {
            float2 e = upk2(O2[i][dd]);
            Es[(tx * 4 + dd) * 132 + r] = (e.x + e.y) * inv;
        }
    }
    __syncthreads();
    float* AOg = g_AO + ((size_t)b * CC + h * DD) * TT;
    for (int idx = tid; idx < DD * 32; idx += 256) {
        const int j  = idx >> 5;
        const int r4 = (idx & 31) << 2;
        *(float4*)&AOg[(size_t)j * TT + t0 + r4] = *(const float4*)&Es[j * 132 + r4];
    }
}

// =====================================================================
extern "C" void kernel_launch(void* const* d_in, const int* in_sizes, int n_in,
                              void* d_out, int out_size)
{
    (void)in_sizes; (void)n_in; (void)out_size;
    const float* x    = (const float*)d_in[0];
    const int*   mask = (const int*)  d_in[1];
    const float* Wq   = (const float*)d_in[2];
    const float* bq   = (const float*)d_in[3];
    const float* Wk   = (const float*)d_in[4];
    const float* bk   = (const float*)d_in[5];
    const float* Wv   = (const float*)d_in[6];
    const float* bv   = (const float*)d_in[7];
    const float* Wo   = (const float*)d_in[8];
    const float* bo   = (const float*)d_in[9];
    const float* emk  = (const float*)d_in[10];
    const float* emv  = (const float*)d_in[11];
    float* out = (float*)d_out;

    cudaFuncSetAttribute(attn_kernel,
                         cudaFuncAttributeMaxDynamicSharedMemorySize,
                         (int)sizeof(AttnSmem));

    dim3 g1(TT / 128, CC / 128, BB * 3);
    qkv_kernel<<<g1, 256>>>(x, Wq, bq, Wk, bk, Wv, bv);

    dim3 g2(TT / 128, BB * HH);
    attn_kernel<<<g2, 256, sizeof(AttnSmem)>>>(mask, emk, emv);

    dim3 g3(TT / 128, CC / 128, BB);
    outproj_kernel<<<g3, 256>>>(Wo, bo, out);
}

// round 9
// speedup vs baseline: 1.3172x; 1.3172x over previous
#include <cuda_runtime.h>

#define BB 4
#define CC 512
#define TT 1024
#define HH 8
#define DD 64
#define WW 4

typedef unsigned long long u64;

// ---------------- device scratch (no runtime allocation allowed) ----------------
__device__ float g_Q [BB*CC*TT];   // [B][C][T]
__device__ float g_K [BB*CC*TT];
__device__ float g_V [BB*CC*TT];
__device__ float g_AO[BB*CC*TT];

// ---------------- packed f32x2 helpers ----------------
__device__ __forceinline__ u64 pk2(float x, float y) {
    u64 r; asm("mov.b64 %0, {%1, %2};" : "=l"(r) : "f"(x), "f"(y)); return r;
}
__device__ __forceinline__ u64 dup2(float x) {
    u64 r; asm("mov.b64 %0, {%1, %1};" : "=l"(r) : "f"(x)); return r;
}
__device__ __forceinline__ void fma2(u64 &d, u64 a, u64 b) {
    asm("fma.rn.f32x2 %0, %1, %2, %0;" : "+l"(d) : "l"(a), "l"(b));
}
__device__ __forceinline__ void mul2(u64 &d, u64 a) {
    asm("mul.rn.f32x2 %0, %0, %1;" : "+l"(d) : "l"(a));
}
__device__ __forceinline__ float2 upk2(u64 v) {
    float2 f; asm("mov.b64 {%0, %1}, %2;" : "=f"(f.x), "=f"(f.y) : "l"(v)); return f;
}

// =====================================================================
// 128x128x16 SGEMM, double-buffered smem, f32x2 core.
// Split-key B columns: thread covers cols {tx*4..+3} and {64+tx*4..+3}
// (conflict-free LDS: tx*4 mod 32 spreads over banks; tx*8 did not).
// =====================================================================
__device__ __forceinline__ void gemm128(const float* __restrict__ Xb,
                                        const float* __restrict__ Wm,
                                        const float* __restrict__ bias,
                                        float* __restrict__ Yb,
                                        int o0, int t0)
{
    __shared__ float As[2][16][132];
    __shared__ float Bs[2][16][132];

    const int tid = threadIdx.x;
    const int ty  = tid >> 4, tx = tid & 15;
    const int am  = tid >> 1;
    const int ak  = (tid & 1) << 3;
    const int bkr = tid >> 4;
    const int bn  = (tid & 15) << 3;

    const float* wp = Wm + (size_t)(o0 + am) * CC + ak;
    const float* xp = Xb + (size_t)bkr * TT + t0 + bn;

    u64 acc[4][8];
#pragma unroll
    for (int i = 0; i < 4; i++)
#pragma unroll
        for (int j = 0; j < 8; j++) acc[i][j] = 0ull;

    {
        float4 a0 = *(const float4*)(wp);
        float4 a1 = *(const float4*)(wp + 4);
        float4 b0 = *(const float4*)(xp);
        float4 b1 = *(const float4*)(xp + 4);
        As[0][ak+0][am]=a0.x; As[0][ak+1][am]=a0.y; As[0][ak+2][am]=a0.z; As[0][ak+3][am]=a0.w;
        As[0][ak+4][am]=a1.x; As[0][ak+5][am]=a1.y; As[0][ak+6][am]=a1.z; As[0][ak+7][am]=a1.w;
        *(float4*)&Bs[0][bkr][bn]     = b0;
        *(float4*)&Bs[0][bkr][bn + 4] = b1;
    }
    __syncthreads();

    const int NCH = CC / 16;
    for (int ch = 0; ch < NCH; ch++) {
        const int cur = ch & 1;
        float4 na0, na1, nb0, nb1;
        if (ch + 1 < NCH) {
            const float* wq = wp + (ch + 1) * 16;
            const float* xq = xp + (size_t)(ch + 1) * 16 * TT;
            na0 = *(const float4*)(wq);
            na1 = *(const float4*)(wq + 4);
            nb0 = *(const float4*)(xq);
            nb1 = *(const float4*)(xq + 4);
        }

#pragma unroll
        for (int k = 0; k < 16; k++) {
            float4 fa0 = *(const float4*)&As[cur][k][ty * 8];
            float4 fa1 = *(const float4*)&As[cur][k][ty * 8 + 4];
            float4 fb0 = *(const float4*)&Bs[cur][k][tx * 4];        // cols tx*4..+3
            float4 fb1 = *(const float4*)&Bs[cur][k][64 + tx * 4];   // cols 64+tx*4..+3
            u64 ap[4] = { pk2(fa0.x, fa0.y), pk2(fa0.z, fa0.w),
                          pk2(fa1.x, fa1.y), pk2(fa1.z, fa1.w) };
            float bb[8] = { fb0.x, fb0.y, fb0.z, fb0.w, fb1.x, fb1.y, fb1.z, fb1.w };
#pragma unroll
            for (int j = 0; j < 8; j++) {
                u64 bd = dup2(bb[j]);
#pragma unroll
                for (int i = 0; i < 4; i++) fma2(acc[i][j], ap[i], bd);
            }
        }

        if (ch + 1 < NCH) {
            const int nxt = cur ^ 1;
            As[nxt][ak+0][am]=na0.x; As[nxt][ak+1][am]=na0.y; As[nxt][ak+2][am]=na0.z; As[nxt][ak+3][am]=na0.w;
            As[nxt][ak+4][am]=na1.x; As[nxt][ak+5][am]=na1.y; As[nxt][ak+6][am]=na1.z; As[nxt][ak+7][am]=na1.w;
            *(float4*)&Bs[nxt][bkr][bn]     = nb0;
            *(float4*)&Bs[nxt][bkr][bn + 4] = nb1;
            __syncthreads();
        }
    }

#pragma unroll
    for (int i = 0; i < 4; i++) {
        const int o = o0 + ty * 8 + 2 * i;
        const float bl = bias[o], bh = bias[o + 1];
        float lo[8], hi[8];
#pragma unroll
        for (int j = 0; j < 8; j++) {
            float2 e = upk2(acc[i][j]);
            lo[j] = e.x + bl; hi[j] = e.y + bh;
        }
        float* y0a = Yb + (size_t)o * TT + t0 + tx * 4;
        float* y0b = Yb + (size_t)o * TT + t0 + 64 + tx * 4;
        *(float4*)y0a        = make_float4(lo[0], lo[1], lo[2], lo[3]);
        *(float4*)y0b        = make_float4(lo[4], lo[5], lo[6], lo[7]);
        *(float4*)(y0a + TT) = make_float4(hi[0], hi[1], hi[2], hi[3]);
        *(float4*)(y0b + TT) = make_float4(hi[4], hi[5], hi[6], hi[7]);
    }
}

__global__ void __launch_bounds__(256, 2)
qkv_kernel(const float* __restrict__ x,
           const float* __restrict__ Wq, const float* __restrict__ bq,
           const float* __restrict__ Wk, const float* __restrict__ bk,
           const float* __restrict__ Wv, const float* __restrict__ bv)
{
    const int z = blockIdx.z;
    const int m = z % 3;
    const int b = z / 3;
    const float* Wm = (m == 0) ? Wq : (m == 1) ? Wk : Wv;
    const float* bm = (m == 0) ? bq : (m == 1) ? bk : bv;
    float* dst      = (m == 0) ? g_Q : (m == 1) ? g_K : g_V;
    gemm128(x + (size_t)b * CC * TT, Wm, bm, dst + (size_t)b * CC * TT,
            blockIdx.y << 7, blockIdx.x << 7);
}

__global__ void __launch_bounds__(256, 2)
outproj_kernel(const float* __restrict__ Wo, const float* __restrict__ bo,
               float* __restrict__ out)
{
    const int b = blockIdx.z;
    gemm128(g_AO + (size_t)b * CC * TT, Wo, bo, out + (size_t)b * CC * TT,
            blockIdx.y << 7, blockIdx.x << 7);
}

// =====================================================================
// Flash attention v4: CTA = (b,h, 128 rows), 128-key tiles, 256 threads.
// Thread tile: 8 rows (ty) x 8 keys split {tx*4..+3, 64+tx*4..+3}.
// V stored [key][dim] (conflict-free PV). PV key-paired f32x2 packing.
// =====================================================================
struct AttnSmem {
    float QsT[DD][136];    // [dim][query row], pre-scaled by 1/8
    float KsT[DD][136];    // [dim][key]
    float Vs [128][68];    // [key][dim]
    float Ps [128][132];   // P [row][key]; epilogue reuses as [dim][row]
    float ek [9][DD];
    float ev [9][DD];
    float qrel[128][12];
    int   msk[128];
};

__global__ void __launch_bounds__(256, 1)
attn_kernel(const int* __restrict__ maskp,
            const float* __restrict__ emk,
            const float* __restrict__ emv)
{
    extern __shared__ char sraw[];
    AttnSmem& sm = *reinterpret_cast<AttnSmem*>(sraw);

    const int tid = threadIdx.x;
    const int ty  = tid >> 4;   // 0..15 -> rows ty*8..+7
    const int tx  = tid & 15;   // keys {tx*4..+3, 64+tx*4..+3}; dims tx*4..+3
    const int bh  = blockIdx.y;
    const int b   = bh >> 3;
    const int h   = bh & 7;
    const int t0  = blockIdx.x << 7;

    const float* Qg = g_Q + ((size_t)b * CC + h * DD) * TT;
    const float* Kg = g_K + ((size_t)b * CC + h * DD) * TT;
    const float* Vg = g_V + ((size_t)b * CC + h * DD) * TT;

    for (int idx = tid; idx < 9 * DD; idx += 256) {
        (&sm.ek[0][0])[idx] = emk[idx];
        (&sm.ev[0][0])[idx] = emv[idx];
    }
    for (int idx = tid; idx < DD * 32; idx += 256) {
        const int j  = idx >> 5;
        const int r4 = (idx & 31) << 2;
        float4 q = *(const float4*)&Qg[(size_t)j * TT + t0 + r4];
        q.x *= 0.125f; q.y *= 0.125f; q.z *= 0.125f; q.w *= 0.125f;
        *(float4*)&sm.QsT[j][r4] = q;
    }
    __syncthreads();

    // qrel[r][e] = (Q/8) . ek[e]
    for (int idx = tid; idx < 128 * 9; idx += 256) {
        const int r = idx & 127;
        const int e = idx >> 7;
        float s = 0.0f;
#pragma unroll 8
        for (int j = 0; j < DD; j++) s += sm.QsT[j][r] * sm.ek[e][j];
        sm.qrel[r][e] = s;
    }

    float mrun[8], lrun[8];
    u64 O2[8][4];   // [local row][dim tx*4+dd], key-parity packed partial sums
#pragma unroll
    for (int i = 0; i < 8; i++) { mrun[i] = -1e30f; lrun[i] = 0.0f; }
#pragma unroll
    for (int i = 0; i < 8; i++)
#pragma unroll
        for (int d = 0; d < 4; d++) O2[i][d] = 0ull;

    for (int c0 = 0; c0 < TT; c0 += 128) {
        __syncthreads();   // previous tile's Ps/Vs/KsT reads complete
        for (int idx = tid; idx < DD * 32; idx += 256) {
            const int j  = idx >> 5;
            const int c4 = (idx & 31) << 2;
            *(float4*)&sm.KsT[j][c4] = *(const float4*)&Kg[(size_t)j * TT + c0 + c4];
            float4 v4 = *(const float4*)&Vg[(size_t)j * TT + c0 + c4];
            sm.Vs[c4 + 0][j] = v4.x;
            sm.Vs[c4 + 1][j] = v4.y;
            sm.Vs[c4 + 2][j] = v4.z;
            sm.Vs[c4 + 3][j] = v4.w;
        }
        if (tid < 128) sm.msk[tid] = maskp[b * TT + c0 + tid];
        __syncthreads();

        // ---- S = (Q/8) K^T : 8 rows x (4+4 split keys), rows packed pairs ----
        u64 sv2[4][8];
#pragma unroll
        for (int p = 0; p < 4; p++)
#pragma unroll
            for (int j = 0; j < 8; j++) sv2[p][j] = 0ull;

#pragma unroll 8
        for (int j = 0; j < DD; j++) {
            float4 a0 = *(const float4*)&sm.QsT[j][ty * 8];
            float4 a1 = *(const float4*)&sm.QsT[j][ty * 8 + 4];
            float4 k0 = *(const float4*)&sm.KsT[j][tx * 4];
            float4 k1 = *(const float4*)&sm.KsT[j][64 + tx * 4];
            u64 ap[4] = { pk2(a0.x, a0.y), pk2(a0.z, a0.w),
                          pk2(a1.x, a1.y), pk2(a1.z, a1.w) };
            float bb[8] = { k0.x, k0.y, k0.z, k0.w, k1.x, k1.y, k1.z, k1.w };
#pragma unroll
            for (int jj = 0; jj < 8; jj++) {
                u64 bd = dup2(bb[jj]);
#pragma unroll
                for (int p = 0; p < 4; p++) fma2(sv2[p][jj], ap[p], bd);
            }
        }

        // ---- per-row: band + mask + online softmax + write P ----
        float f[8];
#pragma unroll
        for (int p = 0; p < 4; p++) {
            float rv[2][8];
#pragma unroll
            for (int jj = 0; jj < 8; jj++) {
                float2 e = upk2(sv2[p][jj]);
                rv[0][jj] = e.x;
                rv[1][jj] = e.y;
            }
#pragma unroll
            for (int hf = 0; hf < 2; hf++) {
                const int i = p * 2 + hf;          // local row 0..7
                const int r = ty * 8 + i;
                const int t = t0 + r;
                float* v = rv[hf];
#pragma unroll
                for (int jj = 0; jj < 8; jj++) {
                    const int kc = (jj < 4) ? (tx * 4 + jj) : (64 + tx * 4 + jj - 4);
                    const int e  = c0 + kc - t + WW;
                    if (e >= 0 && e <= 2 * WW) v[jj] += sm.qrel[r][e];
                    if (sm.msk[kc] == 0) v[jj] = -10000.0f;
                }
                float tm = fmaxf(fmaxf(fmaxf(v[0], v[1]), fmaxf(v[2], v[3])),
                                 fmaxf(fmaxf(v[4], v[5]), fmaxf(v[6], v[7])));
#pragma unroll
                for (int o = 1; o < 16; o <<= 1)
                    tm = fmaxf(tm, __shfl_xor_sync(0xffffffffu, tm, o));
                const float mn = fmaxf(mrun[i], tm);
                f[i] = __expf(mrun[i] - mn);
                mrun[i] = mn;
                float rs = 0.0f;
#pragma unroll
                for (int jj = 0; jj < 8; jj++) {
                    const float pe = __expf(v[jj] - mn);
                    v[jj] = pe;
                    rs += pe;
                }
#pragma unroll
                for (int o = 1; o < 16; o <<= 1)
                    rs += __shfl_xor_sync(0xffffffffu, rs, o);
                lrun[i] = lrun[i] * f[i] + rs;
                *(float4*)&sm.Ps[r][tx * 4]      = make_float4(v[0], v[1], v[2], v[3]);
                *(float4*)&sm.Ps[r][64 + tx * 4] = make_float4(v[4], v[5], v[6], v[7]);
            }
        }

        // rescale O accumulators
#pragma unroll
        for (int i = 0; i < 8; i++) {
            u64 fd = dup2(f[i]);
#pragma unroll
            for (int d = 0; d < 4; d++) mul2(O2[i][d], fd);
        }
        __syncthreads();   // full P tile visible

        // ---- O += P V : key-paired f32x2 ----
#pragma unroll 4
        for (int c = 0; c < 128; c += 4) {
            float4 v0 = *(const float4*)&sm.Vs[c + 0][tx * 4];
            float4 v1 = *(const float4*)&sm.Vs[c + 1][tx * 4];
            float4 v2 = *(const float4*)&sm.Vs[c + 2][tx * 4];
            float4 v3 = *(const float4*)&sm.Vs[c + 3][tx * 4];
            u64 va01[4] = { pk2(v0.x, v1.x), pk2(v0.y, v1.y),
                            pk2(v0.z, v1.z), pk2(v0.w, v1.w) };
            u64 va23[4] = { pk2(v2.x, v3.x), pk2(v2.y, v3.y),
                            pk2(v2.z, v3.z), pk2(v2.w, v3.w) };
#pragma unroll
            for (int i = 0; i < 8; i++) {
                float4 pf = *(const float4*)&sm.Ps[ty * 8 + i][c];
                u64 p01 = pk2(pf.x, pf.y);
                u64 p23 = pk2(pf.z, pf.w);
#pragma unroll
                for (int dd = 0; dd < 4; dd++) {
                    fma2(O2[i][dd], p01, va01[dd]);
                    fma2(O2[i][dd], p23, va23[dd]);
                }
            }
        }

        // ---- band value term (lo lane only: final O = lo + hi) ----
        const int dc = c0 - t0;
        if (dc >= -128 && dc <= 128) {
#pragma unroll
            for (int e = 0; e <= 2 * WW; e++) {
                float4 e4 = *(const float4*)&sm.ev[e][tx * 4];
                u64 ed[4] = { dup2(e4.x), dup2(e4.y), dup2(e4.z), dup2(e4.w) };
#pragma unroll
                for (int i = 0; i < 8; i++) {
                    const int c = t0 + ty * 8 + i + e - WW - c0;
                    if (c >= 0 && c < 128) {
                        u64 pp = pk2(sm.Ps[ty * 8 + i][c], 0.0f);
#pragma unroll
                        for (int dd = 0; dd < 4; dd++) fma2(O2[i][dd], pp, ed[dd]);
                    }
                }
            }
        }
    }

    // ---- epilogue: O = (lo+hi)/l, stage transposed, coalesced store ----
    __syncthreads();
    float* Es = &sm.Ps[0][0];   // reuse as [dim][rows], stride 132
#pragma unroll
    for (int i = 0; i < 8; i++) {
        const float inv = 1.0f / lrun[i];
        const int r = ty * 8 + i;
#pragma unroll
        for (int dd = 0; dd < 4; dd++) {
            float2 e = upk2(O2[i][dd]);
            Es[(tx * 4 + dd) * 132 + r] = (e.x + e.y) * inv;
        }
    }
    __syncthreads();
    float* AOg = g_AO + ((size_t)b * CC + h * DD) * TT;
    for (int idx = tid; idx < DD * 32; idx += 256) {
        const int j  = idx >> 5;
        const int r4 = (idx & 31) << 2;
        *(float4*)&AOg[(size_t)j * TT + t0 + r4] = *(const float4*)&Es[j * 132 + r4];
    }
}

// =====================================================================
extern "C" void kernel_launch(void* const* d_in, const int* in_sizes, int n_in,
                              void* d_out, int out_size)
{
    (void)in_sizes; (void)n_in; (void)out_size;
    const float* x    = (const float*)d_in[0];
    const int*   mask = (const int*)  d_in[1];
    const float* Wq   = (const float*)d_in[2];
    const float* bq   = (const float*)d_in[3];
    const float* Wk   = (const float*)d_in[4];
    const float* bk   = (const float*)d_in[5];
    const float* Wv   = (const float*)d_in[6];
    const float* bv   = (const float*)d_in[7];
    const float* Wo   = (const float*)d_in[8];
    const float* bo   = (const float*)d_in[9];
    const float* emk  = (const float*)d_in[10];
    const float* emv  = (const float*)d_in[11];
    float* out = (float*)d_out;

    cudaFuncSetAttribute(attn_kernel,
                         cudaFuncAttributeMaxDynamicSharedMemorySize,
                         (int)sizeof(AttnSmem));

    dim3 g1(TT / 128, CC / 128, BB * 3);
    qkv_kernel<<<g1, 256>>>(x, Wq, bq, Wk, bk, Wv, bv);

    dim3 g2(TT / 128, BB * HH);
    attn_kernel<<<g2, 256, sizeof(AttnSmem)>>>(mask, emk, emv);

    dim3 g3(TT / 128, CC / 128, BB);
    outproj_kernel<<<g3, 256>>>(Wo, bo, out);
}

// round 11
// speedup vs baseline: 1.4409x; 1.0939x over previous
#include <cuda_runtime.h>

#define BB 4
#define CC 512
#define TT 1024
#define HH 8
#define DD 64
#define WW 4

typedef unsigned long long u64;

// ---------------- device scratch (no runtime allocation allowed) ----------------
__device__ float g_Q [BB*CC*TT];   // [B][C][T]
__device__ float g_K [BB*CC*TT];
__device__ float g_V [BB*CC*TT];
__device__ float g_AO[BB*CC*TT];

// ---------------- packed f32x2 helpers ----------------
__device__ __forceinline__ u64 pk2(float x, float y) {
    u64 r; asm("mov.b64 %0, {%1, %2};" : "=l"(r) : "f"(x), "f"(y)); return r;
}
__device__ __forceinline__ u64 dup2(float x) {
    u64 r; asm("mov.b64 %0, {%1, %1};" : "=l"(r) : "f"(x)); return r;
}
__device__ __forceinline__ void fma2(u64 &d, u64 a, u64 b) {
    asm("fma.rn.f32x2 %0, %1, %2, %0;" : "+l"(d) : "l"(a), "l"(b));
}
__device__ __forceinline__ void mul2(u64 &d, u64 a) {
    asm("mul.rn.f32x2 %0, %0, %1;" : "+l"(d) : "l"(a));
}
__device__ __forceinline__ float2 upk2(u64 v) {
    float2 f; asm("mov.b64 {%0, %1}, %2;" : "=f"(f.x), "=f"(f.y) : "l"(v)); return f;
}

// =====================================================================
// 128x128x16 SGEMM, double-buffered smem, f32x2 core, split-key B cols.
// (R9 version verbatim — measured qkv 146.4us / outproj ~48us)
// =====================================================================
__device__ __forceinline__ void gemm128(const float* __restrict__ Xb,
                                        const float* __restrict__ Wm,
                                        const float* __restrict__ bias,
                                        float* __restrict__ Yb,
                                        int o0, int t0)
{
    __shared__ float As[2][16][132];
    __shared__ float Bs[2][16][132];

    const int tid = threadIdx.x;
    const int ty  = tid >> 4, tx = tid & 15;
    const int am  = tid >> 1;
    const int ak  = (tid & 1) << 3;
    const int bkr = tid >> 4;
    const int bn  = (tid & 15) << 3;

    const float* wp = Wm + (size_t)(o0 + am) * CC + ak;
    const float* xp = Xb + (size_t)bkr * TT + t0 + bn;

    u64 acc[4][8];
#pragma unroll
    for (int i = 0; i < 4; i++)
#pragma unroll
        for (int j = 0; j < 8; j++) acc[i][j] = 0ull;

    {
        float4 a0 = *(const float4*)(wp);
        float4 a1 = *(const float4*)(wp + 4);
        float4 b0 = *(const float4*)(xp);
        float4 b1 = *(const float4*)(xp + 4);
        As[0][ak+0][am]=a0.x; As[0][ak+1][am]=a0.y; As[0][ak+2][am]=a0.z; As[0][ak+3][am]=a0.w;
        As[0][ak+4][am]=a1.x; As[0][ak+5][am]=a1.y; As[0][ak+6][am]=a1.z; As[0][ak+7][am]=a1.w;
        *(float4*)&Bs[0][bkr][bn]     = b0;
        *(float4*)&Bs[0][bkr][bn + 4] = b1;
    }
    __syncthreads();

    const int NCH = CC / 16;
    for (int ch = 0; ch < NCH; ch++) {
        const int cur = ch & 1;
        float4 na0, na1, nb0, nb1;
        if (ch + 1 < NCH) {
            const float* wq = wp + (ch + 1) * 16;
            const float* xq = xp + (size_t)(ch + 1) * 16 * TT;
            na0 = *(const float4*)(wq);
            na1 = *(const float4*)(wq + 4);
            nb0 = *(const float4*)(xq);
            nb1 = *(const float4*)(xq + 4);
        }

#pragma unroll
        for (int k = 0; k < 16; k++) {
            float4 fa0 = *(const float4*)&As[cur][k][ty * 8];
            float4 fa1 = *(const float4*)&As[cur][k][ty * 8 + 4];
            float4 fb0 = *(const float4*)&Bs[cur][k][tx * 4];        // cols tx*4..+3
            float4 fb1 = *(const float4*)&Bs[cur][k][64 + tx * 4];   // cols 64+tx*4..+3
            u64 ap[4] = { pk2(fa0.x, fa0.y), pk2(fa0.z, fa0.w),
                          pk2(fa1.x, fa1.y), pk2(fa1.z, fa1.w) };
            float bb[8] = { fb0.x, fb0.y, fb0.z, fb0.w, fb1.x, fb1.y, fb1.z, fb1.w };
#pragma unroll
            for (int j = 0; j < 8; j++) {
                u64 bd = dup2(bb[j]);
#pragma unroll
                for (int i = 0; i < 4; i++) fma2(acc[i][j], ap[i], bd);
            }
        }

        if (ch + 1 < NCH) {
            const int nxt = cur ^ 1;
            As[nxt][ak+0][am]=na0.x; As[nxt][ak+1][am]=na0.y; As[nxt][ak+2][am]=na0.z; As[nxt][ak+3][am]=na0.w;
            As[nxt][ak+4][am]=na1.x; As[nxt][ak+5][am]=na1.y; As[nxt][ak+6][am]=na1.z; As[nxt][ak+7][am]=na1.w;
            *(float4*)&Bs[nxt][bkr][bn]     = nb0;
            *(float4*)&Bs[nxt][bkr][bn + 4] = nb1;
            __syncthreads();
        }
    }

#pragma unroll
    for (int i = 0; i < 4; i++) {
        const int o = o0 + ty * 8 + 2 * i;
        const float bl = bias[o], bh = bias[o + 1];
        float lo[8], hi[8];
#pragma unroll
        for (int j = 0; j < 8; j++) {
            float2 e = upk2(acc[i][j]);
            lo[j] = e.x + bl; hi[j] = e.y + bh;
        }
        float* y0a = Yb + (size_t)o * TT + t0 + tx * 4;
        float* y0b = Yb + (size_t)o * TT + t0 + 64 + tx * 4;
        *(float4*)y0a        = make_float4(lo[0], lo[1], lo[2], lo[3]);
        *(float4*)y0b        = make_float4(lo[4], lo[5], lo[6], lo[7]);
        *(float4*)(y0a + TT) = make_float4(hi[0], hi[1], hi[2], hi[3]);
        *(float4*)(y0b + TT) = make_float4(hi[4], hi[5], hi[6], hi[7]);
    }
}

__global__ void __launch_bounds__(256, 2)
qkv_kernel(const float* __restrict__ x,
           const float* __restrict__ Wq, const float* __restrict__ bq,
           const float* __restrict__ Wk, const float* __restrict__ bk,
           const float* __restrict__ Wv, const float* __restrict__ bv)
{
    const int z = blockIdx.z;
    const int m = z % 3;
    const int b = z / 3;
    const float* Wm = (m == 0) ? Wq : (m == 1) ? Wk : Wv;
    const float* bm = (m == 0) ? bq : (m == 1) ? bk : bv;
    float* dst      = (m == 0) ? g_Q : (m == 1) ? g_K : g_V;
    gemm128(x + (size_t)b * CC * TT, Wm, bm, dst + (size_t)b * CC * TT,
            blockIdx.y << 7, blockIdx.x << 7);
}

__global__ void __launch_bounds__(256, 2)
outproj_kernel(const float* __restrict__ Wo, const float* __restrict__ bo,
               float* __restrict__ out)
{
    const int b = blockIdx.z;
    gemm128(g_AO + (size_t)b * CC * TT, Wo, bo, out + (size_t)b * CC * TT,
            blockIdx.y << 7, blockIdx.x << 7);
}

// =====================================================================
// Flash attention (R7 measured-best config): CTA = (b,h, 64 rows),
// 64-wide key tiles, 256 threads, 4x4 micro-tiles, f32x2, 2 CTAs/SM.
// CHANGE vs R7: V tile loaded via register-gather transpose
// (coalesced LDG.32 + conflict-free STS.128) instead of 8-way-conflicted
// scalar STS scatter.
// =====================================================================
struct AttnSmem {
    float QsT[DD][68];
    float KsT[DD][68];
    float Vs [64][68];
    float Ps [64][68];
    float ek [9][DD];
    float ev [9][DD];
    float qrel[64][12];
    int   msk[64];
};

__global__ void __launch_bounds__(256, 2)
attn_kernel(const int* __restrict__ maskp,
            const float* __restrict__ emk,
            const float* __restrict__ emv)
{
    extern __shared__ char sraw[];
    AttnSmem& sm = *reinterpret_cast<AttnSmem*>(sraw);

    const int tid = threadIdx.x;
    const int ty  = tid >> 4;
    const int tx  = tid & 15;
    const int bh  = blockIdx.y;
    const int b   = bh >> 3;
    const int h   = bh & 7;
    const int t0  = blockIdx.x << 6;

    const float* Qg = g_Q + ((size_t)b * CC + h * DD) * TT;
    const float* Kg = g_K + ((size_t)b * CC + h * DD) * TT;
    const float* Vg = g_V + ((size_t)b * CC + h * DD) * TT;

    // V register-gather mapping: thread owns one key, 4 dim-groups
    const int vkey = tid & 63;
    const int vg0  = tid >> 6;    // 0..3

    for (int idx = tid; idx < 9 * DD; idx += 256) {
        (&sm.ek[0][0])[idx] = emk[idx];
        (&sm.ev[0][0])[idx] = emv[idx];
    }
    for (int idx = tid; idx < DD * 16; idx += 256) {
        const int j  = idx >> 4;
        const int c4 = idx & 15;
        float4 q = *(const float4*)&Qg[(size_t)j * TT + t0 + c4 * 4];
        q.x *= 0.125f; q.y *= 0.125f; q.z *= 0.125f; q.w *= 0.125f;
        *(float4*)&sm.QsT[j][c4 * 4] = q;
    }
    __syncthreads();

    // qrel[r][e] = (Q/8) . ek[e]
    for (int idx = tid; idx < 64 * 9; idx += 256) {
        const int r = idx & 63;
        const int e = idx >> 6;
        float s = 0.0f;
#pragma unroll 8
        for (int j = 0; j < DD; j++) s += sm.QsT[j][r] * sm.ek[e][j];
        sm.qrel[r][e] = s;
    }

    float mrun[4], lrun[4];
    u64 O2[2][4];
#pragma unroll
    for (int i = 0; i < 4; i++) { mrun[i] = -1e30f; lrun[i] = 0.0f; }
#pragma unroll
    for (int p = 0; p < 2; p++)
#pragma unroll
        for (int j = 0; j < 4; j++) O2[p][j] = 0ull;

    for (int c0 = 0; c0 < TT; c0 += 64) {
        __syncthreads();
        // K tile: dim-major float4 (coalesced, conflict-free)
        for (int idx = tid; idx < DD * 16; idx += 256) {
            const int j  = idx >> 4;
            const int c4 = idx & 15;
            *(float4*)&sm.KsT[j][c4 * 4] = *(const float4*)&Kg[(size_t)j * TT + c0 + c4 * 4];
        }
        // V tile: register-gather transpose -> Vs[key][dim]
        // lanes have consecutive keys => LDG.32 coalesced; STS.128 bank stride
        // 68 words => 8-lane phases hit banks {4k} (conflict-free)
#pragma unroll
        for (int g = 0; g < 4; g++) {
            const int gg = vg0 + g * 4;           // dim group 0..15
            const float* vp = Vg + (size_t)(gg * 4) * TT + c0 + vkey;
            float4 v4;
            v4.x = vp[0 * TT];
            v4.y = vp[1 * TT];
            v4.z = vp[2 * TT];
            v4.w = vp[3 * TT];
            *(float4*)&sm.Vs[vkey][gg * 4] = v4;
        }
        if (tid < 64) sm.msk[tid] = maskp[b * TT + c0 + tid];
        __syncthreads();

        // ---- S = (Q/8) K^T ----
        u64 sv2[2][4];
#pragma unroll
        for (int p = 0; p < 2; p++)
#pragma unroll
            for (int j = 0; j < 4; j++) sv2[p][j] = 0ull;

#pragma unroll 8
        for (int j = 0; j < DD; j++) {
            float4 a  = *(const float4*)&sm.QsT[j][ty * 4];
            float4 k4 = *(const float4*)&sm.KsT[j][tx * 4];
            u64 ap0 = pk2(a.x, a.y);
            u64 ap1 = pk2(a.z, a.w);
            u64 bd;
            bd = dup2(k4.x); fma2(sv2[0][0], ap0, bd); fma2(sv2[1][0], ap1, bd);
            bd = dup2(k4.y); fma2(sv2[0][1], ap0, bd); fma2(sv2[1][1], ap1, bd);
            bd = dup2(k4.z); fma2(sv2[0][2], ap0, bd); fma2(sv2[1][2], ap1, bd);
            bd = dup2(k4.w); fma2(sv2[0][3], ap0, bd); fma2(sv2[1][3], ap1, bd);
        }

        float sv[4][4];
#pragma unroll
        for (int jj = 0; jj < 4; jj++) {
            float2 e0 = upk2(sv2[0][jj]);
            float2 e1 = upk2(sv2[1][jj]);
            sv[0][jj] = e0.x; sv[1][jj] = e0.y;
            sv[2][jj] = e1.x; sv[3][jj] = e1.y;
        }

        // ---- band score + mask ----
#pragma unroll
        for (int i = 0; i < 4; i++) {
            const int t = t0 + ty * 4 + i;
#pragma unroll
            for (int jj = 0; jj < 4; jj++) {
                const int s = c0 + tx * 4 + jj;
                const int e = s - t + WW;
                float v = sv[i][jj];
                if (e >= 0 && e <= 2 * WW) v += sm.qrel[ty * 4 + i][e];
                if (sm.msk[tx * 4 + jj] == 0) v = -10000.0f;
                sv[i][jj] = v;
            }
        }

        // ---- online softmax ----
        float f[4];
#pragma unroll
        for (int i = 0; i < 4; i++) {
            float tm = fmaxf(fmaxf(sv[i][0], sv[i][1]), fmaxf(sv[i][2], sv[i][3]));
#pragma unroll
            for (int o = 1; o < 16; o <<= 1)
                tm = fmaxf(tm, __shfl_xor_sync(0xffffffffu, tm, o));
            const float mn = fmaxf(mrun[i], tm);
            f[i] = __expf(mrun[i] - mn);
            mrun[i] = mn;
        }
#pragma unroll
        for (int i = 0; i < 4; i++) {
            float rs = 0.0f;
#pragma unroll
            for (int jj = 0; jj < 4; jj++) {
                const float p = __expf(sv[i][jj] - mrun[i]);
                sv[i][jj] = p;
                rs += p;
            }
#pragma unroll
            for (int o = 1; o < 16; o <<= 1)
                rs += __shfl_xor_sync(0xffffffffu, rs, o);
            lrun[i] = lrun[i] * f[i] + rs;
        }
        {
            u64 f01 = pk2(f[0], f[1]);
            u64 f23 = pk2(f[2], f[3]);
#pragma unroll
            for (int jj = 0; jj < 4; jj++) { mul2(O2[0][jj], f01); mul2(O2[1][jj], f23); }
        }

#pragma unroll
        for (int i = 0; i < 4; i++)
#pragma unroll
            for (int jj = 0; jj < 4; jj++)
                sm.Ps[ty * 4 + i][tx * 4 + jj] = sv[i][jj];
        __syncthreads();

        // ---- O += P V ----
#pragma unroll 4
        for (int c = 0; c < 64; c += 4) {
            float P0[4], P1[4], P2[4], P3[4];
            *(float4*)P0 = *(const float4*)&sm.Ps[ty * 4 + 0][c];
            *(float4*)P1 = *(const float4*)&sm.Ps[ty * 4 + 1][c];
            *(float4*)P2 = *(const float4*)&sm.Ps[ty * 4 + 2][c];
            *(float4*)P3 = *(const float4*)&sm.Ps[ty * 4 + 3][c];
#pragma unroll
            for (int cc = 0; cc < 4; cc++) {
                float4 v = *(const float4*)&sm.Vs[c + cc][tx * 4];
                u64 pp0 = pk2(P0[cc], P1[cc]);
                u64 pp1 = pk2(P2[cc], P3[cc]);
                u64 vd;
                vd = dup2(v.x); fma2(O2[0][0], pp0, vd); fma2(O2[1][0], pp1, vd);
                vd = dup2(v.y); fma2(O2[0][1], pp0, vd); fma2(O2[1][1], pp1, vd);
                vd = dup2(v.z); fma2(O2[0][2], pp0, vd); fma2(O2[1][2], pp1, vd);
                vd = dup2(v.w); fma2(O2[0][3], pp0, vd); fma2(O2[1][3], pp1, vd);
            }
        }

        // ---- band value term ----
        const int dc = c0 - t0;
        if (dc >= -64 && dc <= 64) {
#pragma unroll
            for (int e = 0; e <= 2 * WW; e++) {
                float4 e4 = *(const float4*)&sm.ev[e][tx * 4];
                const int cb = t0 + ty * 4 + e - WW - c0;
                float pr[4];
#pragma unroll
                for (int i = 0; i < 4; i++) {
                    const int c = cb + i;
                    pr[i] = (c >= 0 && c < 64) ? sm.Ps[ty * 4 + i][c] : 0.0f;
                }
                u64 pp0 = pk2(pr[0], pr[1]);
                u64 pp1 = pk2(pr[2], pr[3]);
                u64 vd;
                vd = dup2(e4.x); fma2(O2[0][0], pp0, vd); fma2(O2[1][0], pp1, vd);
                vd = dup2(e4.y); fma2(O2[0][1], pp0, vd); fma2(O2[1][1], pp1, vd);
                vd = dup2(e4.z); fma2(O2[0][2], pp0, vd); fma2(O2[1][2], pp1, vd);
                vd = dup2(e4.w); fma2(O2[0][3], pp0, vd); fma2(O2[1][3], pp1, vd);
            }
        }
    }

    // ---- epilogue ----
    __syncthreads();
    {
        const float i0 = 1.0f / lrun[0], i1 = 1.0f / lrun[1];
        const float i2 = 1.0f / lrun[2], i3 = 1.0f / lrun[3];
#pragma unroll
        for (int jj = 0; jj < 4; jj++) {
            float2 e0 = upk2(O2[0][jj]);
            float2 e1 = upk2(O2[1][jj]);
            sm.Ps[tx * 4 + jj][ty * 4 + 0] = e0.x * i0;
            sm.Ps[tx * 4 + jj][ty * 4 + 1] = e0.y * i1;
            sm.Ps[tx * 4 + jj][ty * 4 + 2] = e1.x * i2;
            sm.Ps[tx * 4 + jj][ty * 4 + 3] = e1.y * i3;
        }
    }
    __syncthreads();
    float* AOg = g_AO + ((size_t)b * CC + h * DD) * TT;
    for (int idx = tid; idx < 64 * 16; idx += 256) {
        const int j  = idx >> 4;
        const int r4 = (idx & 15) * 4;
        float4 o4 = *(const float4*)&sm.Ps[j][r4];
        *(float4*)&AOg[(size_t)j * TT + t0 + r4] = o4;
    }
}

// =====================================================================
extern "C" void kernel_launch(void* const* d_in, const int* in_sizes, int n_in,
                              void* d_out, int out_size)
{
    (void)in_sizes; (void)n_in; (void)out_size;
    const float* x    = (const float*)d_in[0];
    const int*   mask = (const int*)  d_in[1];
    const float* Wq   = (const float*)d_in[2];
    const float* bq   = (const float*)d_in[3];
    const float* Wk   = (const float*)d_in[4];
    const float* bk   = (const float*)d_in[5];
    const float* Wv   = (const float*)d_in[6];
    const float* bv   = (const float*)d_in[7];
    const float* Wo   = (const float*)d_in[8];
    const float* bo   = (const float*)d_in[9];
    const float* emk  = (const float*)d_in[10];
    const float* emv  = (const float*)d_in[11];
    float* out = (float*)d_out;

    cudaFuncSetAttribute(attn_kernel,
                         cudaFuncAttributeMaxDynamicSharedMemorySize,
                         (int)sizeof(AttnSmem));

    dim3 g1(TT / 128, CC / 128, BB * 3);
    qkv_kernel<<<g1, 256>>>(x, Wq, bq, Wk, bk, Wv, bv);

    dim3 g2(TT / 64, BB * HH);
    attn_kernel<<<g2, 256, sizeof(AttnSmem)>>>(mask, emk, emv);

    dim3 g3(TT / 128, CC / 128, BB);
    outproj_kernel<<<g3, 256>>>(Wo, bo, out);
}

// round 12
// speedup vs baseline: 1.4686x; 1.0192x over previous
#include <cuda_runtime.h>

#define BB 4
#define CC 512
#define TT 1024
#define HH 8
#define DD 64
#define WW 4

typedef unsigned long long u64;

// ---------------- device scratch (no runtime allocation allowed) ----------------
__device__ float g_Q [BB*CC*TT];   // [B][C][T]
__device__ float g_K [BB*CC*TT];
__device__ float g_V [BB*CC*TT];
__device__ float g_AO[BB*CC*TT];

// ---------------- packed f32x2 helpers ----------------
__device__ __forceinline__ u64 pk2(float x, float y) {
    u64 r; asm("mov.b64 %0, {%1, %2};" : "=l"(r) : "f"(x), "f"(y)); return r;
}
__device__ __forceinline__ u64 dup2(float x) {
    u64 r; asm("mov.b64 %0, {%1, %1};" : "=l"(r) : "f"(x)); return r;
}
__device__ __forceinline__ void fma2(u64 &d, u64 a, u64 b) {
    asm("fma.rn.f32x2 %0, %1, %2, %0;" : "+l"(d) : "l"(a), "l"(b));
}
__device__ __forceinline__ void mul2(u64 &d, u64 a) {
    asm("mul.rn.f32x2 %0, %0, %1;" : "+l"(d) : "l"(a));
}
__device__ __forceinline__ float2 upk2(u64 v) {
    float2 f; asm("mov.b64 {%0, %1}, %2;" : "=f"(f.x), "=f"(f.y) : "l"(v)); return f;
}

// =====================================================================
// 128x128x16 SGEMM, double-buffered smem, f32x2 core, split-key B cols.
// (R9/R11 version verbatim — measured qkv 146us / outproj ~50us)
// =====================================================================
__device__ __forceinline__ void gemm128(const float* __restrict__ Xb,
                                        const float* __restrict__ Wm,
                                        const float* __restrict__ bias,
                                        float* __restrict__ Yb,
                                        int o0, int t0)
{
    __shared__ float As[2][16][132];
    __shared__ float Bs[2][16][132];

    const int tid = threadIdx.x;
    const int ty  = tid >> 4, tx = tid & 15;
    const int am  = tid >> 1;
    const int ak  = (tid & 1) << 3;
    const int bkr = tid >> 4;
    const int bn  = (tid & 15) << 3;

    const float* wp = Wm + (size_t)(o0 + am) * CC + ak;
    const float* xp = Xb + (size_t)bkr * TT + t0 + bn;

    u64 acc[4][8];
#pragma unroll
    for (int i = 0; i < 4; i++)
#pragma unroll
        for (int j = 0; j < 8; j++) acc[i][j] = 0ull;

    {
        float4 a0 = *(const float4*)(wp);
        float4 a1 = *(const float4*)(wp + 4);
        float4 b0 = *(const float4*)(xp);
        float4 b1 = *(const float4*)(xp + 4);
        As[0][ak+0][am]=a0.x; As[0][ak+1][am]=a0.y; As[0][ak+2][am]=a0.z; As[0][ak+3][am]=a0.w;
        As[0][ak+4][am]=a1.x; As[0][ak+5][am]=a1.y; As[0][ak+6][am]=a1.z; As[0][ak+7][am]=a1.w;
        *(float4*)&Bs[0][bkr][bn]     = b0;
        *(float4*)&Bs[0][bkr][bn + 4] = b1;
    }
    __syncthreads();

    const int NCH = CC / 16;
    for (int ch = 0; ch < NCH; ch++) {
        const int cur = ch & 1;
        float4 na0, na1, nb0, nb1;
        if (ch + 1 < NCH) {
            const float* wq = wp + (ch + 1) * 16;
            const float* xq = xp + (size_t)(ch + 1) * 16 * TT;
            na0 = *(const float4*)(wq);
            na1 = *(const float4*)(wq + 4);
            nb0 = *(const float4*)(xq);
            nb1 = *(const float4*)(xq + 4);
        }

#pragma unroll
        for (int k = 0; k < 16; k++) {
            float4 fa0 = *(const float4*)&As[cur][k][ty * 8];
            float4 fa1 = *(const float4*)&As[cur][k][ty * 8 + 4];
            float4 fb0 = *(const float4*)&Bs[cur][k][tx * 4];
            float4 fb1 = *(const float4*)&Bs[cur][k][64 + tx * 4];
            u64 ap[4] = { pk2(fa0.x, fa0.y), pk2(fa0.z, fa0.w),
                          pk2(fa1.x, fa1.y), pk2(fa1.z, fa1.w) };
            float bb[8] = { fb0.x, fb0.y, fb0.z, fb0.w, fb1.x, fb1.y, fb1.z, fb1.w };
#pragma unroll
            for (int j = 0; j < 8; j++) {
                u64 bd = dup2(bb[j]);
#pragma unroll
                for (int i = 0; i < 4; i++) fma2(acc[i][j], ap[i], bd);
            }
        }

        if (ch + 1 < NCH) {
            const int nxt = cur ^ 1;
            As[nxt][ak+0][am]=na0.x; As[nxt][ak+1][am]=na0.y; As[nxt][ak+2][am]=na0.z; As[nxt][ak+3][am]=na0.w;
            As[nxt][ak+4][am]=na1.x; As[nxt][ak+5][am]=na1.y; As[nxt][ak+6][am]=na1.z; As[nxt][ak+7][am]=na1.w;
            *(float4*)&Bs[nxt][bkr][bn]     = nb0;
            *(float4*)&Bs[nxt][bkr][bn + 4] = nb1;
            __syncthreads();
        }
    }

#pragma unroll
    for (int i = 0; i < 4; i++) {
        const int o = o0 + ty * 8 + 2 * i;
        const float bl = bias[o], bh = bias[o + 1];
        float lo[8], hi[8];
#pragma unroll
        for (int j = 0; j < 8; j++) {
            float2 e = upk2(acc[i][j]);
            lo[j] = e.x + bl; hi[j] = e.y + bh;
        }
        float* y0a = Yb + (size_t)o * TT + t0 + tx * 4;
        float* y0b = Yb + (size_t)o * TT + t0 + 64 + tx * 4;
        *(float4*)y0a        = make_float4(lo[0], lo[1], lo[2], lo[3]);
        *(float4*)y0b        = make_float4(lo[4], lo[5], lo[6], lo[7]);
        *(float4*)(y0a + TT) = make_float4(hi[0], hi[1], hi[2], hi[3]);
        *(float4*)(y0b + TT) = make_float4(hi[4], hi[5], hi[6], hi[7]);
    }
}

__global__ void __launch_bounds__(256, 2)
qkv_kernel(const float* __restrict__ x,
           const float* __restrict__ Wq, const float* __restrict__ bq,
           const float* __restrict__ Wk, const float* __restrict__ bk,
           const float* __restrict__ Wv, const float* __restrict__ bv)
{
    const int z = blockIdx.z;
    const int m = z % 3;
    const int b = z / 3;
    const float* Wm = (m == 0) ? Wq : (m == 1) ? Wk : Wv;
    const float* bm = (m == 0) ? bq : (m == 1) ? bk : bv;
    float* dst      = (m == 0) ? g_Q : (m == 1) ? g_K : g_V;
    gemm128(x + (size_t)b * CC * TT, Wm, bm, dst + (size_t)b * CC * TT,
            blockIdx.y << 7, blockIdx.x << 7);
}

__global__ void __launch_bounds__(256, 2)
outproj_kernel(const float* __restrict__ Wo, const float* __restrict__ bo,
               float* __restrict__ out)
{
    const int b = blockIdx.z;
    gemm128(g_AO + (size_t)b * CC * TT, Wo, bo, out + (size_t)b * CC * TT,
            blockIdx.y << 7, blockIdx.x << 7);
}

// =====================================================================
// Flash attention v5: CTA = (b,h, 64 query rows), 128-wide key tiles,
// 256 threads (ty 16 x tx 16), micro-tile 4 rows x 8 split keys.
// Ps aliases KsT (K dead after S) -> 95.3KB smem -> 2 CTAs/SM.
// smem float offsets:
//   QsT   0      [64][68]   (dim-major Q, pre-scaled 1/8)
//   KsT   4352   [64][136]  (dim-major K, 128 keys)   } aliased
//   Ps    4352   [64][132]  (P tile, row-major)       }
//   Vs    13056  [128][68]  (key-major V)
//   ek    21760  [9][64]
//   ev    22336  [9][64]
//   qrel  22912  [64][12]
//   msk   23680  int[128]
// total 23808 floats = 95232 B
// =====================================================================
#define ATTN_SMEM_BYTES 95232

__global__ void __launch_bounds__(256, 2)
attn_kernel(const int* __restrict__ maskp,
            const float* __restrict__ emk,
            const float* __restrict__ emv)
{
    extern __shared__ float sf[];
    float* QsT  = sf;            // stride 68
    float* KsT  = sf + 4352;     // stride 136
    float* Ps   = sf + 4352;     // stride 132 (aliases KsT)
    float* Vs   = sf + 13056;    // stride 68
    float* ek   = sf + 21760;    // [9][64]
    float* ev   = sf + 22336;    // [9][64]
    float* qrel = sf + 22912;    // stride 12
    int*   msk  = (int*)(sf + 23680);

    const int tid = threadIdx.x;
    const int ty  = tid >> 4;    // 0..15 -> rows ty*4..+3
    const int tx  = tid & 15;    // keys {tx*4..+3, 64+tx*4..+3}; dims tx*4..+3
    const int bh  = blockIdx.y;
    const int b   = bh >> 3;
    const int h   = bh & 7;
    const int t0  = blockIdx.x << 6;

    const float* Qg = g_Q + ((size_t)b * CC + h * DD) * TT;
    const float* Kg = g_K + ((size_t)b * CC + h * DD) * TT;
    const float* Vg = g_V + ((size_t)b * CC + h * DD) * TT;

    // V register-gather mapping: thread owns one key (0..127), 8 dim-groups
    const int vkey  = tid & 127;
    const int vhalf = tid >> 7;   // 0/1 -> dim groups 0..7 / 8..15

    for (int idx = tid; idx < 9 * DD; idx += 256) {
        ek[idx] = emk[idx];
        ev[idx] = emv[idx];
    }
    // Q tile: 64 dims x 64 rows, float4, pre-scaled by 1/8
    for (int idx = tid; idx < DD * 16; idx += 256) {
        const int j  = idx >> 4;
        const int r4 = (idx & 15) * 4;
        float4 q = *(const float4*)&Qg[(size_t)j * TT + t0 + r4];
        q.x *= 0.125f; q.y *= 0.125f; q.z *= 0.125f; q.w *= 0.125f;
        *(float4*)&QsT[j * 68 + r4] = q;
    }
    __syncthreads();

    // qrel[r][e] = (Q/8) . ek[e]
    for (int idx = tid; idx < 64 * 9; idx += 256) {
        const int r = idx & 63;
        const int e = idx >> 6;
        float s = 0.0f;
#pragma unroll 8
        for (int j = 0; j < DD; j++) s += QsT[j * 68 + r] * ek[e * 64 + j];
        qrel[r * 12 + e] = s;
    }

    float mrun[4], lrun[4];
    u64 O2[2][4];   // row-pairs (0/1),(2/3) x dims tx*4+dd
#pragma unroll
    for (int i = 0; i < 4; i++) { mrun[i] = -1e30f; lrun[i] = 0.0f; }
#pragma unroll
    for (int p = 0; p < 2; p++)
#pragma unroll
        for (int j = 0; j < 4; j++) O2[p][j] = 0ull;

    for (int c0 = 0; c0 < TT; c0 += 128) {
        __syncthreads();   // prev PV/band reads of Ps/Vs done; qrel ready (1st iter)
        // K tile: 64 dims x 128 keys, float4 coalesced
        for (int idx = tid; idx < DD * 32; idx += 256) {
            const int j  = idx >> 5;
            const int c4 = (idx & 31) * 4;
            *(float4*)&KsT[j * 136 + c4] = *(const float4*)&Kg[(size_t)j * TT + c0 + c4];
        }
        // V tile: register-gather transpose -> Vs[key][dim]
#pragma unroll
        for (int g = 0; g < 8; g++) {
            const int gg = vhalf * 8 + g;    // dim group 0..15
            const float* vp = Vg + (size_t)(gg * 4) * TT + c0 + vkey;
            float4 v4;
            v4.x = vp[0 * TT];
            v4.y = vp[1 * TT];
            v4.z = vp[2 * TT];
            v4.w = vp[3 * TT];
            *(float4*)&Vs[vkey * 68 + gg * 4] = v4;
        }
        if (tid < 128) msk[tid] = maskp[b * TT + c0 + tid];
        __syncthreads();

        // ---- S = (Q/8) K^T : 4 rows x 8 split keys, rows packed in pairs ----
        u64 sv2[2][8];
#pragma unroll
        for (int p = 0; p < 2; p++)
#pragma unroll
            for (int j = 0; j < 8; j++) sv2[p][j] = 0ull;

#pragma unroll 8
        for (int j = 0; j < DD; j++) {
            float4 a  = *(const float4*)&QsT[j * 68 + ty * 4];
            float4 k0 = *(const float4*)&KsT[j * 136 + tx * 4];
            float4 k1 = *(const float4*)&KsT[j * 136 + 64 + tx * 4];
            u64 ap0 = pk2(a.x, a.y);
            u64 ap1 = pk2(a.z, a.w);
            float bb[8] = { k0.x, k0.y, k0.z, k0.w, k1.x, k1.y, k1.z, k1.w };
#pragma unroll
            for (int jj = 0; jj < 8; jj++) {
                u64 bd = dup2(bb[jj]);
                fma2(sv2[0][jj], ap0, bd);
                fma2(sv2[1][jj], ap1, bd);
            }
        }
        __syncthreads();   // all K reads done before P overwrites the buffer

        // ---- per-row: band + mask + online softmax + write P ----
        float f[4];
#pragma unroll
        for (int p = 0; p < 2; p++) {
            float rv[2][8];
#pragma unroll
            for (int jj = 0; jj < 8; jj++) {
                float2 e = upk2(sv2[p][jj]);
                rv[0][jj] = e.x;
                rv[1][jj] = e.y;
            }
#pragma unroll
            for (int hf = 0; hf < 2; hf++) {
                const int i = p * 2 + hf;        // local row 0..3
                const int r = ty * 4 + i;
                const int t = t0 + r;
                float* v = rv[hf];
#pragma unroll
                for (int jj = 0; jj < 8; jj++) {
                    const int kc = (jj < 4) ? (tx * 4 + jj) : (64 + tx * 4 + jj - 4);
                    const int e  = c0 + kc - t + WW;
                    if (e >= 0 && e <= 2 * WW) v[jj] += qrel[r * 12 + e];
                    if (msk[kc] == 0) v[jj] = -10000.0f;
                }
                float tm = fmaxf(fmaxf(fmaxf(v[0], v[1]), fmaxf(v[2], v[3])),
                                 fmaxf(fmaxf(v[4], v[5]), fmaxf(v[6], v[7])));
#pragma unroll
                for (int o = 1; o < 16; o <<= 1)
                    tm = fmaxf(tm, __shfl_xor_sync(0xffffffffu, tm, o));
                const float mn = fmaxf(mrun[i], tm);
                f[i] = __expf(mrun[i] - mn);
                mrun[i] = mn;
                float rs = 0.0f;
#pragma unroll
                for (int jj = 0; jj < 8; jj++) {
                    const float pe = __expf(v[jj] - mn);
                    v[jj] = pe;
                    rs += pe;
                }
#pragma unroll
                for (int o = 1; o < 16; o <<= 1)
                    rs += __shfl_xor_sync(0xffffffffu, rs, o);
                lrun[i] = lrun[i] * f[i] + rs;
                *(float4*)&Ps[r * 132 + tx * 4]      = make_float4(v[0], v[1], v[2], v[3]);
                *(float4*)&Ps[r * 132 + 64 + tx * 4] = make_float4(v[4], v[5], v[6], v[7]);
            }
        }

        // rescale O accumulators
        {
            u64 f01 = pk2(f[0], f[1]);
            u64 f23 = pk2(f[2], f[3]);
#pragma unroll
            for (int jj = 0; jj < 4; jj++) { mul2(O2[0][jj], f01); mul2(O2[1][jj], f23); }
        }
        __syncthreads();   // full P tile visible

        // ---- O += P V ----
#pragma unroll 4
        for (int c = 0; c < 128; c += 4) {
            float P0[4], P1[4], P2[4], P3[4];
            *(float4*)P0 = *(const float4*)&Ps[(ty * 4 + 0) * 132 + c];
            *(float4*)P1 = *(const float4*)&Ps[(ty * 4 + 1) * 132 + c];
            *(float4*)P2 = *(const float4*)&Ps[(ty * 4 + 2) * 132 + c];
            *(float4*)P3 = *(const float4*)&Ps[(ty * 4 + 3) * 132 + c];
#pragma unroll
            for (int cc = 0; cc < 4; cc++) {
                float4 v = *(const float4*)&Vs[(c + cc) * 68 + tx * 4];
                u64 pp0 = pk2(P0[cc], P1[cc]);
                u64 pp1 = pk2(P2[cc], P3[cc]);
                u64 vd;
                vd = dup2(v.x); fma2(O2[0][0], pp0, vd); fma2(O2[1][0], pp1, vd);
                vd = dup2(v.y); fma2(O2[0][1], pp0, vd); fma2(O2[1][1], pp1, vd);
                vd = dup2(v.z); fma2(O2[0][2], pp0, vd); fma2(O2[1][2], pp1, vd);
                vd = dup2(v.w); fma2(O2[0][3], pp0, vd); fma2(O2[1][3], pp1, vd);
            }
        }

        // ---- band value term (tiles overlapping |s-t|<=4 only) ----
        const int dc = c0 - t0;
        if (dc >= -128 && dc <= 64) {
#pragma unroll
            for (int e = 0; e <= 2 * WW; e++) {
                float4 e4 = *(const float4*)&ev[e * 64 + tx * 4];
                const int cb = t0 + ty * 4 + e - WW - c0;
                float pr[4];
#pragma unroll
                for (int i = 0; i < 4; i++) {
                    const int c = cb + i;
                    pr[i] = (c >= 0 && c < 128) ? Ps[(ty * 4 + i) * 132 + c] : 0.0f;
                }
                u64 pp0 = pk2(pr[0], pr[1]);
                u64 pp1 = pk2(pr[2], pr[3]);
                u64 vd;
                vd = dup2(e4.x); fma2(O2[0][0], pp0, vd); fma2(O2[1][0], pp1, vd);
                vd = dup2(e4.y); fma2(O2[0][1], pp0, vd); fma2(O2[1][1], pp1, vd);
                vd = dup2(e4.z); fma2(O2[0][2], pp0, vd); fma2(O2[1][2], pp1, vd);
                vd = dup2(e4.w); fma2(O2[0][3], pp0, vd); fma2(O2[1][3], pp1, vd);
            }
        }
    }

    // ---- epilogue: normalize, stage transposed [dim][row], coalesced store ----
    __syncthreads();
    {
        const float i0 = 1.0f / lrun[0], i1 = 1.0f / lrun[1];
        const float i2 = 1.0f / lrun[2], i3 = 1.0f / lrun[3];
#pragma unroll
        for (int jj = 0; jj < 4; jj++) {
            float2 e0 = upk2(O2[0][jj]);
            float2 e1 = upk2(O2[1][jj]);
            Ps[(tx * 4 + jj) * 132 + ty * 4 + 0] = e0.x * i0;
            Ps[(tx * 4 + jj) * 132 + ty * 4 + 1] = e0.y * i1;
            Ps[(tx * 4 + jj) * 132 + ty * 4 + 2] = e1.x * i2;
            Ps[(tx * 4 + jj) * 132 + ty * 4 + 3] = e1.y * i3;
        }
    }
    __syncthreads();
    float* AOg = g_AO + ((size_t)b * CC + h * DD) * TT;
    for (int idx = tid; idx < DD * 16; idx += 256) {
        const int j  = idx >> 4;
        const int r4 = (idx & 15) * 4;
        *(float4*)&AOg[(size_t)j * TT + t0 + r4] = *(const float4*)&Ps[j * 132 + r4];
    }
}

// =====================================================================
extern "C" void kernel_launch(void* const* d_in, const int* in_sizes, int n_in,
                              void* d_out, int out_size)
{
    (void)in_sizes; (void)n_in; (void)out_size;
    const float* x    = (const float*)d_in[0];
    const int*   mask = (const int*)  d_in[1];
    const float* Wq   = (const float*)d_in[2];
    const float* bq   = (const float*)d_in[3];
    const float* Wk   = (const float*)d_in[4];
    const float* bk   = (const float*)d_in[5];
    const float* Wv   = (const float*)d_in[6];
    const float* bv   = (const float*)d_in[7];
    const float* Wo   = (const float*)d_in[8];
    const float* bo   = (const float*)d_in[9];
    const float* emk  = (const float*)d_in[10];
    const float* emv  = (const float*)d_in[11];
    float* out = (float*)d_out;

    cudaFuncSetAttribute(attn_kernel,
                         cudaFuncAttributeMaxDynamicSharedMemorySize,
                         ATTN_SMEM_BYTES);

    dim3 g1(TT / 128, CC / 128, BB * 3);
    qkv_kernel<<<g1, 256>>>(x, Wq, bq, Wk, bk, Wv, bv);

    dim3 g2(TT / 64, BB * HH);
    attn_kernel<<<g2, 256, ATTN_SMEM_BYTES>>>(mask, emk, emv);

    dim3 g3(TT / 128, CC / 128, BB);
    outproj_kernel<<<g3, 256>>>(Wo, bo, out);
}